// round 13
// baseline (speedup 1.0000x reference)
#include <cuda_runtime.h>

// LearnedBFGSSolver — 2-kernel pipeline:
//  kz: [U0|V0] = Y @ [H0^T | H0] fused tiled GEMM. 32x64 tiles, grid 288
//      (96 row-blocks x 3 col-blocks), 256 thr, ~2 CTAs/SM.
//  fe: fused epilogue — per-pair Grams + 12x12 scalar recursion + rebuild
//      (A, Un in SMEM, in-place over U0/V0), then rank-24 GEMM
//      H = H0 + S^T A + Un^T S. grid 768 (3 x 64-row blocks per pair).

#define NN 192
#define TT 12
#define BE 256

typedef unsigned long long u64;

__device__ float g_U0[TT * BE * NN];   // row r = t*BE+be (same order as dgs rows)
__device__ float g_V0[TT * BE * NN];

__device__ __forceinline__ u64 fma2(u64 a, u64 b, u64 c) {
    u64 d; asm("fma.rn.f32x2 %0, %1, %2, %3;" : "=l"(d) : "l"(a), "l"(b), "l"(c));
    return d;
}
__device__ __forceinline__ u64 pack2(float lo, float hi) {
    u64 d; asm("mov.b64 %0, {%1, %2};" : "=l"(d) : "f"(lo), "f"(hi));
    return d;
}
__device__ __forceinline__ void unpack2(u64 v, float& lo, float& hi) {
    asm("mov.b64 {%0, %1}, %2;" : "=f"(lo), "=f"(hi) : "l"(v));
}

// ---------------- K1: kz — fused double GEMM, 32x64 tiles ----------------
// U0[r][i] = sum_j Y[r][j] H0[i][j],  V0[r][i] = sum_j Y[r][j] H0[j][i].
__global__ void __launch_bounds__(256, 2)
kz_kernel(const float* __restrict__ H0g, const float* __restrict__ dgs)
{
    __shared__ float sYt[32][36];   // sYt[jj][rr] = Y[r0+rr][j0+jj]
    __shared__ float sBu[32][68];   // sBu[jj][ii] = H0[i0+ii][j0+jj]
    __shared__ float sBv[32][68];   // sBv[jj][ii] = H0[j0+jj][i0+ii]
    const int tid = threadIdx.x;
    const int rb = blockIdx.x % 96, cb = blockIdx.x / 96;
    const int r0 = rb * 32, i0 = cb * 64;
    const int cgi = tid & 15;       // cols i0 + cgi*4 .. +3
    const int rgi = tid >> 4;       // rows r0 + rgi*2 .. +1

    u64 aU[2][2], aV[2][2];
    #pragma unroll
    for (int r = 0; r < 2; r++) {
        aU[r][0] = 0ull; aU[r][1] = 0ull;
        aV[r][0] = 0ull; aV[r][1] = 0ull;
    }

    for (int jt = 0; jt < 6; jt++) {
        const int j0 = jt * 32;
        __syncthreads();
        // sYt: 32x32 transposed scatter (256 float4 = 1/thread)
        {
            int rr = tid >> 3, q = tid & 7;
            float4 y4 = *(const float4*)&dgs[(size_t)(r0 + rr) * NN + j0 + 4 * q];
            sYt[4 * q + 0][rr] = y4.x;
            sYt[4 * q + 1][rr] = y4.y;
            sYt[4 * q + 2][rr] = y4.z;
            sYt[4 * q + 3][rr] = y4.w;
        }
        // sBu: H0[i0:i0+64][j0:j0+32] transposed scatter (512 float4)
        #pragma unroll
        for (int n = 0; n < 2; n++) {
            int idx = n * 256 + tid;
            int ii = idx >> 3, q = idx & 7;
            float4 h4 = *(const float4*)&H0g[(size_t)(i0 + ii) * NN + j0 + 4 * q];
            sBu[4 * q + 0][ii] = h4.x;
            sBu[4 * q + 1][ii] = h4.y;
            sBu[4 * q + 2][ii] = h4.z;
            sBu[4 * q + 3][ii] = h4.w;
        }
        // sBv: H0[j0:j0+32][i0:i0+64] direct float4 (512 float4)
        #pragma unroll
        for (int n = 0; n < 2; n++) {
            int idx = n * 256 + tid;
            int jj = idx >> 4, q = idx & 15;
            float4 h4 = *(const float4*)&H0g[(size_t)(j0 + jj) * NN + i0 + 4 * q];
            *(float4*)&sBv[jj][4 * q] = h4;
        }
        __syncthreads();

        #pragma unroll 4
        for (int jj = 0; jj < 32; jj++) {
            float2 yf = *(const float2*)&sYt[jj][rgi * 2];
            ulonglong2 bu = *(const ulonglong2*)&sBu[jj][cgi * 4];
            ulonglong2 bv = *(const ulonglong2*)&sBv[jj][cgi * 4];
            u64 y0 = pack2(yf.x, yf.x);
            u64 y1 = pack2(yf.y, yf.y);
            aU[0][0] = fma2(y0, bu.x, aU[0][0]);
            aU[0][1] = fma2(y0, bu.y, aU[0][1]);
            aU[1][0] = fma2(y1, bu.x, aU[1][0]);
            aU[1][1] = fma2(y1, bu.y, aU[1][1]);
            aV[0][0] = fma2(y0, bv.x, aV[0][0]);
            aV[0][1] = fma2(y0, bv.y, aV[0][1]);
            aV[1][0] = fma2(y1, bv.x, aV[1][0]);
            aV[1][1] = fma2(y1, bv.y, aV[1][1]);
        }
    }

    #pragma unroll
    for (int rr = 0; rr < 2; rr++) {
        size_t off = (size_t)(r0 + rgi * 2 + rr) * NN + i0 + cgi * 4;
        float4 uo, vo;
        unpack2(aU[rr][0], uo.x, uo.y);
        unpack2(aU[rr][1], uo.z, uo.w);
        unpack2(aV[rr][0], vo.x, vo.y);
        unpack2(aV[rr][1], vo.z, vo.w);
        *(float4*)&g_U0[off] = uo;
        *(float4*)&g_V0[off] = vo;
    }
}

// ---------------- K2: fe — fused recursion + rank-24 epilogue ----------------
// grid = 256 pairs * 3 row-blocks (64 rows); 192 threads.
// After rebuild, sV holds A and sU holds Un (in-place).
__global__ void __launch_bounds__(192)
fe_kernel(const float* __restrict__ H0g,
          const float* __restrict__ steps,
          const float* __restrict__ dgs,
          float* __restrict__ out)
{
    __shared__ float sS[TT][NN], sY[TT][NN], sU[TT][NN], sV[TT][NN];
    __shared__ float sG1[TT][TT], sW[TT][TT];
    __shared__ float sCU[TT][TT], sCV[TT][TT], sB[TT][TT];
    __shared__ float sC1[TT], sC2[TT];

    const int tid  = threadIdx.x;
    const int be   = blockIdx.x / 3;
    const int rblk = (blockIdx.x % 3) * 64;

    for (int idx = tid; idx < TT * NN / 4; idx += 192) {
        int e = idx * 4;
        int k = e / NN, j = e % NN;
        size_t roff = (size_t)(k * BE + be) * NN + j;
        *(float4*)&sS[k][j] = *(const float4*)&steps[roff];
        *(float4*)&sY[k][j] = *(const float4*)&dgs[roff];
        *(float4*)&sU[k][j] = *(const float4*)&g_U0[roff];
        *(float4*)&sV[k][j] = *(const float4*)&g_V0[roff];
    }
    __syncthreads();

    // Grams: G1 = S Y^T, W = V0 Y^T  (2x2 cells per thread, 72 threads)
    if (tid < 72) {
        int which = tid / 36;
        int cell  = tid % 36;
        int k0 = (cell / 6) * 2, t0 = (cell % 6) * 2;
        const float (*P)[NN] = which ? sV : sS;
        float a00 = 0.f, a01 = 0.f, a10 = 0.f, a11 = 0.f;
        for (int j = 0; j < NN; j += 4) {
            float4 p0 = *(const float4*)&P[k0][j];
            float4 p1 = *(const float4*)&P[k0 + 1][j];
            float4 q0 = *(const float4*)&sY[t0][j];
            float4 q1 = *(const float4*)&sY[t0 + 1][j];
            a00 += p0.x * q0.x + p0.y * q0.y + p0.z * q0.z + p0.w * q0.w;
            a01 += p0.x * q1.x + p0.y * q1.y + p0.z * q1.z + p0.w * q1.w;
            a10 += p1.x * q0.x + p1.y * q0.y + p1.z * q0.z + p1.w * q0.w;
            a11 += p1.x * q1.x + p1.y * q1.y + p1.z * q1.z + p1.w * q1.w;
        }
        float (*G)[TT] = which ? sW : sG1;
        G[k0][t0] = a00;     G[k0][t0 + 1] = a01;
        G[k0 + 1][t0] = a10; G[k0 + 1][t0 + 1] = a11;
    }
    __syncthreads();

    // Warp-0 scalar recursion, lane = column t
    if (tid < 32) {
        const int t = (tid < TT) ? tid : (TT - 1);
        float G1c[TT], Wc[TT], Wr[TT];
        float d2c[TT], d3c[TT];
        float c1v[TT], c2v[TT];
        float cuL[TT], cvL[TT], bL[TT];
        #pragma unroll
        for (int m = 0; m < TT; m++) {
            G1c[m] = sG1[m][t];
            Wc[m]  = sW[m][t];
            Wr[m]  = sW[t][m];
            cuL[m] = 0.f; cvL[m] = 0.f; bL[m] = 0.f;
        }
        #pragma unroll
        for (int k = 0; k < TT; k++) {
            if (k > 0) {
                const int m = k - 1;
                cuL[m] = c1v[m] * G1c[m] - c2v[m] * d2c[m];
                cvL[m] = c1v[m] * G1c[m] - c2v[m] * d3c[m];
                bL[m]  = -c2v[m] * G1c[m];
            }
            float x2 = Wc[k], x3 = Wr[k];
            #pragma unroll
            for (int m = 0; m < TT - 1; m++) {
                if (m < k) {
                    float cvk = __shfl_sync(0xFFFFFFFFu, cvL[m], k);
                    float cuk = __shfl_sync(0xFFFFFFFFu, cuL[m], k);
                    float bk  = __shfl_sync(0xFFFFFFFFu, bL[m],  k);
                    x2 += cvk * G1c[m] + bk * d2c[m];
                    x3 += cuk * G1c[m] + bk * d3c[m];
                }
            }
            d2c[k] = x2;
            d3c[k] = x3;
            float yHy  = __shfl_sync(0xFFFFFFFFu, x3, k);
            float sdot = __shfl_sync(0xFFFFFFFFu, G1c[k], k);
            float ic = (sdot != 0.0f) ? (1.0f / sdot) : 0.0f;
            c2v[k] = ic;
            c1v[k] = (sdot + yHy) * ic * ic;
        }
        if (tid < TT) {
            #pragma unroll
            for (int m = 0; m < TT - 1; m++) {
                sCU[m][t] = cuL[m];
                sCV[m][t] = cvL[m];
                sB[m][t]  = bL[m];
            }
        }
        if (tid == 0) {
            #pragma unroll
            for (int m = 0; m < TT; m++) { sC1[m] = c1v[m]; sC2[m] = c2v[m]; }
        }
    }
    __syncthreads();

    // In-place rebuild: thread i reads its column into regs, writes A -> sV,
    // Un -> sU (same column). No cross-thread aliasing.
    {
        const int i = tid;
        float s[TT], u[TT], v[TT];
        #pragma unroll
        for (int k = 0; k < TT; k++) {
            s[k] = sS[k][i];
            u[k] = sU[k][i];
            v[k] = sV[k][i];
        }
        #pragma unroll
        for (int t = 0; t < TT; t++) {
            #pragma unroll
            for (int k = 0; k < TT - 1; k++) {
                if (k < t) {
                    float bb = sB[k][t];
                    u[t] += sCU[k][t] * s[k] + bb * u[k];
                    v[t] += sCV[k][t] * s[k] + bb * v[k];
                }
            }
            float c1 = sC1[t], c2 = sC2[t];
            sV[t][i] = c1 * s[t] - c2 * v[t];   // A
            sU[t][i] = -c2 * u[t];              // Un
        }
    }
    __syncthreads();

    // Rank-24 GEMM: H = H0 + S^T A + Un^T S.
    // cg = tid>>3 (8 lanes broadcast one column address), rg = tid&7.
    const int cg = tid >> 3, rg = tid & 7;
    const int c0   = cg * 8;
    const int grow = rblk + rg * 8;
    float* ob = out + (size_t)be * NN * NN;

    u64 acc[8][4];
    #pragma unroll
    for (int r = 0; r < 8; r++) {
        ulonglong2 h01 = *(const ulonglong2*)&H0g[(size_t)(grow + r) * NN + c0];
        ulonglong2 h23 = *(const ulonglong2*)&H0g[(size_t)(grow + r) * NN + c0 + 4];
        acc[r][0] = h01.x; acc[r][1] = h01.y; acc[r][2] = h23.x; acc[r][3] = h23.y;
    }
    #pragma unroll
    for (int k = 0; k < TT; k++) {
        ulonglong2 a01 = *(ulonglong2*)&sV[k][c0];       // A columns
        ulonglong2 a23 = *(ulonglong2*)&sV[k][c0 + 4];
        ulonglong2 s01 = *(ulonglong2*)&sS[k][c0];       // S columns
        ulonglong2 s23 = *(ulonglong2*)&sS[k][c0 + 4];
        u64 av[4] = {a01.x, a01.y, a23.x, a23.y};
        u64 sv[4] = {s01.x, s01.y, s23.x, s23.y};
        float4 sr0 = *(float4*)&sS[k][grow];
        float4 sr1 = *(float4*)&sS[k][grow + 4];
        float4 ur0 = *(float4*)&sU[k][grow];             // Un rows
        float4 ur1 = *(float4*)&sU[k][grow + 4];
        float srow[8] = {sr0.x, sr0.y, sr0.z, sr0.w, sr1.x, sr1.y, sr1.z, sr1.w};
        float urow[8] = {ur0.x, ur0.y, ur0.z, ur0.w, ur1.x, ur1.y, ur1.z, ur1.w};
        #pragma unroll
        for (int r = 0; r < 8; r++) {
            u64 s2 = pack2(srow[r], srow[r]);
            u64 u2 = pack2(urow[r], urow[r]);
            #pragma unroll
            for (int c = 0; c < 4; c++) {
                acc[r][c] = fma2(s2, av[c], acc[r][c]);
                acc[r][c] = fma2(u2, sv[c], acc[r][c]);
            }
        }
    }
    #pragma unroll
    for (int r = 0; r < 8; r++) {
        *(ulonglong2*)&ob[(size_t)(grow + r) * NN + c0] =
            make_ulonglong2(acc[r][0], acc[r][1]);
        *(ulonglong2*)&ob[(size_t)(grow + r) * NN + c0 + 4] =
            make_ulonglong2(acc[r][2], acc[r][3]);
    }
}

extern "C" void kernel_launch(void* const* d_in, const int* in_sizes, int n_in,
                              void* d_out, int out_size) {
    const float* H0    = (const float*)d_in[0];   // inv_hessian [192,192]
    const float* steps = (const float*)d_in[1];   // [12,8,32,192]
    const float* dgs   = (const float*)d_in[2];   // [12,8,32,192]
    float* out = (float*)d_out;                   // [8,32,192,192]

    kz_kernel<<<288, 256>>>(H0, dgs);
    fe_kernel<<<BE * 3, 192>>>(H0, steps, dgs, out);
}

// round 14
// speedup vs baseline: 1.3499x; 1.3499x over previous
#include <cuda_runtime.h>

// LearnedBFGSSolver — 3 kernels (best measured structure, R12) + fixes:
//  kz: [U0|V0] = Y @ [H0^T | H0] fused tiled GEMM, 32x64 tiles, grid 288.
//  ks: per-pair Grams (bank-conflict-free padded rows) -> 12x12 scalar
//      recursion -> factor vectors A, Un.
//  ke: H = H0 + S^T A + Un^T S rank-24 GEMM, conflict-free, grid 768.

#define NN 192
#define NP 196          // padded row stride (784 B = 16 mod 128 -> bank rotate)
#define TT 12
#define BE 256

typedef unsigned long long u64;

__device__ float g_U0[TT * BE * NN];   // row r = t*BE+be (same order as dgs rows)
__device__ float g_V0[TT * BE * NN];
__device__ float g_A [BE * TT * NN];   // [be][k][j]
__device__ float g_Un[BE * TT * NN];

__device__ __forceinline__ u64 fma2(u64 a, u64 b, u64 c) {
    u64 d; asm("fma.rn.f32x2 %0, %1, %2, %3;" : "=l"(d) : "l"(a), "l"(b), "l"(c));
    return d;
}
__device__ __forceinline__ u64 pack2(float lo, float hi) {
    u64 d; asm("mov.b64 %0, {%1, %2};" : "=l"(d) : "f"(lo), "f"(hi));
    return d;
}
__device__ __forceinline__ void unpack2(u64 v, float& lo, float& hi) {
    asm("mov.b64 {%0, %1}, %2;" : "=f"(lo), "=f"(hi) : "l"(v));
}

// ---------------- K1: kz — fused double GEMM, 32x64 tiles, grid 288 ----------------
// U0[r][i] = sum_j Y[r][j] H0[i][j],  V0[r][i] = sum_j Y[r][j] H0[j][i].
__global__ void __launch_bounds__(256, 2)
kz_kernel(const float* __restrict__ H0g, const float* __restrict__ dgs)
{
    __shared__ float sYt[32][36];   // sYt[jj][rr] = Y[r0+rr][j0+jj]
    __shared__ float sBu[32][68];   // sBu[jj][ii] = H0[i0+ii][j0+jj]
    __shared__ float sBv[32][68];   // sBv[jj][ii] = H0[j0+jj][i0+ii]
    const int tid = threadIdx.x;
    const int rb = blockIdx.x % 96, cb = blockIdx.x / 96;
    const int r0 = rb * 32, i0 = cb * 64;
    const int cgi = tid & 15;       // cols i0 + cgi*4 .. +3
    const int rgi = tid >> 4;       // rows r0 + rgi*2 .. +1

    u64 aU[2][2], aV[2][2];
    #pragma unroll
    for (int r = 0; r < 2; r++) {
        aU[r][0] = 0ull; aU[r][1] = 0ull;
        aV[r][0] = 0ull; aV[r][1] = 0ull;
    }

    for (int jt = 0; jt < 6; jt++) {
        const int j0 = jt * 32;
        __syncthreads();
        {   // sYt: 32x32 transposed scatter (1 float4/thread)
            int rr = tid >> 3, q = tid & 7;
            float4 y4 = *(const float4*)&dgs[(size_t)(r0 + rr) * NN + j0 + 4 * q];
            sYt[4 * q + 0][rr] = y4.x;
            sYt[4 * q + 1][rr] = y4.y;
            sYt[4 * q + 2][rr] = y4.z;
            sYt[4 * q + 3][rr] = y4.w;
        }
        #pragma unroll
        for (int n = 0; n < 2; n++) {   // sBu: transposed scatter
            int idx = n * 256 + tid;
            int ii = idx >> 3, q = idx & 7;
            float4 h4 = *(const float4*)&H0g[(size_t)(i0 + ii) * NN + j0 + 4 * q];
            sBu[4 * q + 0][ii] = h4.x;
            sBu[4 * q + 1][ii] = h4.y;
            sBu[4 * q + 2][ii] = h4.z;
            sBu[4 * q + 3][ii] = h4.w;
        }
        #pragma unroll
        for (int n = 0; n < 2; n++) {   // sBv: direct float4
            int idx = n * 256 + tid;
            int jj = idx >> 4, q = idx & 15;
            float4 h4 = *(const float4*)&H0g[(size_t)(j0 + jj) * NN + i0 + 4 * q];
            *(float4*)&sBv[jj][4 * q] = h4;
        }
        __syncthreads();

        #pragma unroll 4
        for (int jj = 0; jj < 32; jj++) {
            float2 yf = *(const float2*)&sYt[jj][rgi * 2];
            ulonglong2 bu = *(const ulonglong2*)&sBu[jj][cgi * 4];
            ulonglong2 bv = *(const ulonglong2*)&sBv[jj][cgi * 4];
            u64 y0 = pack2(yf.x, yf.x);
            u64 y1 = pack2(yf.y, yf.y);
            aU[0][0] = fma2(y0, bu.x, aU[0][0]);
            aU[0][1] = fma2(y0, bu.y, aU[0][1]);
            aU[1][0] = fma2(y1, bu.x, aU[1][0]);
            aU[1][1] = fma2(y1, bu.y, aU[1][1]);
            aV[0][0] = fma2(y0, bv.x, aV[0][0]);
            aV[0][1] = fma2(y0, bv.y, aV[0][1]);
            aV[1][0] = fma2(y1, bv.x, aV[1][0]);
            aV[1][1] = fma2(y1, bv.y, aV[1][1]);
        }
    }

    #pragma unroll
    for (int rr = 0; rr < 2; rr++) {
        size_t off = (size_t)(r0 + rgi * 2 + rr) * NN + i0 + cgi * 4;
        float4 uo, vo;
        unpack2(aU[rr][0], uo.x, uo.y);
        unpack2(aU[rr][1], uo.z, uo.w);
        unpack2(aV[rr][0], vo.x, vo.y);
        unpack2(aV[rr][1], vo.z, vo.w);
        *(float4*)&g_U0[off] = uo;
        *(float4*)&g_V0[off] = vo;
    }
}

// ---------------- K2: ks — per-pair recursion, padded (conflict-free) rows ----------------
__global__ void __launch_bounds__(192)
ks_kernel(const float* __restrict__ steps, const float* __restrict__ dgs)
{
    __shared__ float sS[TT][NP], sY[TT][NP], sU0[TT][NP], sV0[TT][NP];
    __shared__ float sG1[TT][TT], sW[TT][TT];
    __shared__ float sCU[TT][TT], sCV[TT][TT], sB[TT][TT];
    __shared__ float sC1[TT], sC2[TT];

    const int tid = threadIdx.x;
    const int be  = blockIdx.x;

    for (int idx = tid; idx < TT * NN / 4; idx += 192) {
        int e = idx * 4;
        int k = e / NN, j = e % NN;
        size_t roff = (size_t)(k * BE + be) * NN + j;
        *(float4*)&sS[k][j]  = *(const float4*)&steps[roff];
        *(float4*)&sY[k][j]  = *(const float4*)&dgs[roff];
        *(float4*)&sU0[k][j] = *(const float4*)&g_U0[roff];
        *(float4*)&sV0[k][j] = *(const float4*)&g_V0[roff];
    }
    __syncthreads();

    // Grams: G1 = S Y^T, W = V0 Y^T (2x2 cells/thread, 72 threads, padded rows)
    if (tid < 72) {
        int which = tid / 36;
        int cell  = tid % 36;
        int k0 = (cell / 6) * 2, t0 = (cell % 6) * 2;
        const float (*P)[NP] = which ? sV0 : sS;
        float a00 = 0.f, a01 = 0.f, a10 = 0.f, a11 = 0.f;
        for (int j = 0; j < NN; j += 4) {
            float4 p0 = *(const float4*)&P[k0][j];
            float4 p1 = *(const float4*)&P[k0 + 1][j];
            float4 q0 = *(const float4*)&sY[t0][j];
            float4 q1 = *(const float4*)&sY[t0 + 1][j];
            a00 += p0.x * q0.x + p0.y * q0.y + p0.z * q0.z + p0.w * q0.w;
            a01 += p0.x * q1.x + p0.y * q1.y + p0.z * q1.z + p0.w * q1.w;
            a10 += p1.x * q0.x + p1.y * q0.y + p1.z * q0.z + p1.w * q0.w;
            a11 += p1.x * q1.x + p1.y * q1.y + p1.z * q1.z + p1.w * q1.w;
        }
        float (*G)[TT] = which ? sW : sG1;
        G[k0][t0] = a00;     G[k0][t0 + 1] = a01;
        G[k0 + 1][t0] = a10; G[k0 + 1][t0 + 1] = a11;
    }
    __syncthreads();

    // Warp-0 scalar recursion, lane = column t
    if (tid < 32) {
        const int t = (tid < TT) ? tid : (TT - 1);
        float G1c[TT], Wc[TT], Wr[TT];
        float d2c[TT], d3c[TT];
        float c1v[TT], c2v[TT];
        float cuL[TT], cvL[TT], bL[TT];
        #pragma unroll
        for (int m = 0; m < TT; m++) {
            G1c[m] = sG1[m][t];
            Wc[m]  = sW[m][t];
            Wr[m]  = sW[t][m];
            cuL[m] = 0.f; cvL[m] = 0.f; bL[m] = 0.f;
        }
        #pragma unroll
        for (int k = 0; k < TT; k++) {
            if (k > 0) {
                const int m = k - 1;
                cuL[m] = c1v[m] * G1c[m] - c2v[m] * d2c[m];
                cvL[m] = c1v[m] * G1c[m] - c2v[m] * d3c[m];
                bL[m]  = -c2v[m] * G1c[m];
            }
            float x2 = Wc[k], x3 = Wr[k];
            #pragma unroll
            for (int m = 0; m < TT - 1; m++) {
                if (m < k) {
                    float cvk = __shfl_sync(0xFFFFFFFFu, cvL[m], k);
                    float cuk = __shfl_sync(0xFFFFFFFFu, cuL[m], k);
                    float bk  = __shfl_sync(0xFFFFFFFFu, bL[m],  k);
                    x2 += cvk * G1c[m] + bk * d2c[m];
                    x3 += cuk * G1c[m] + bk * d3c[m];
                }
            }
            d2c[k] = x2;
            d3c[k] = x3;
            float yHy  = __shfl_sync(0xFFFFFFFFu, x3, k);
            float sdot = __shfl_sync(0xFFFFFFFFu, G1c[k], k);
            float ic = (sdot != 0.0f) ? (1.0f / sdot) : 0.0f;
            c2v[k] = ic;
            c1v[k] = (sdot + yHy) * ic * ic;
        }
        if (tid < TT) {
            #pragma unroll
            for (int m = 0; m < TT - 1; m++) {
                sCU[m][t] = cuL[m];
                sCV[m][t] = cvL[m];
                sB[m][t]  = bL[m];
            }
        }
        if (tid == 0) {
            #pragma unroll
            for (int m = 0; m < TT; m++) { sC1[m] = c1v[m]; sC2[m] = c2v[m]; }
        }
    }
    __syncthreads();

    // Barrier-free per-element rebuild; emit A, Un (be-major)
    {
        const int i = tid;
        float s[TT], u[TT], v[TT];
        #pragma unroll
        for (int k = 0; k < TT; k++) {
            s[k] = sS[k][i];
            u[k] = sU0[k][i];
            v[k] = sV0[k][i];
        }
        #pragma unroll
        for (int t = 0; t < TT; t++) {
            #pragma unroll
            for (int k = 0; k < TT - 1; k++) {
                if (k < t) {
                    float bb = sB[k][t];
                    u[t] += sCU[k][t] * s[k] + bb * u[k];
                    v[t] += sCV[k][t] * s[k] + bb * v[k];
                }
            }
            float c1 = sC1[t], c2 = sC2[t];
            g_A [(size_t)(be * TT + t) * NN + i] = c1 * s[t] - c2 * v[t];
            g_Un[(size_t)(be * TT + t) * NN + i] = -c2 * u[t];
        }
    }
}

// ---------------- K3: ke — rank-24 epilogue GEMM ----------------
// grid = 256 pairs * 3 row-blocks (64 rows); 192 threads; 8x8 f32x2 tiles.
// cg = tid>>3 (8 lanes broadcast one column address), rg = tid&7.
__global__ void __launch_bounds__(192)
ke_kernel(const float* __restrict__ H0g,
          const float* __restrict__ steps,
          float* __restrict__ out)
{
    __shared__ float sA[TT][NN];
    __shared__ float sS[TT][NN];
    __shared__ float sUn[TT][64];
    const int tid  = threadIdx.x;
    const int be   = blockIdx.x / 3;
    const int rblk = (blockIdx.x % 3) * 64;

    for (int idx = tid; idx < TT * NN / 4; idx += 192) {
        int e = idx * 4;
        int k = e / NN, j = e % NN;
        *(float4*)&sA[k][j] = *(const float4*)&g_A[(size_t)(be * TT + k) * NN + j];
        *(float4*)&sS[k][j] = *(const float4*)&steps[(size_t)(k * BE + be) * NN + j];
    }
    {
        int e = tid * 4;
        int k = e / 64, r = e % 64;
        *(float4*)&sUn[k][r] = *(const float4*)&g_Un[(size_t)(be * TT + k) * NN + rblk + r];
    }
    __syncthreads();

    const int cg = tid >> 3, rg = tid & 7;
    const int c0   = cg * 8;
    const int lr0  = rg * 8;
    const int grow = rblk + lr0;
    float* ob = out + (size_t)be * NN * NN;

    u64 acc[8][4];
    #pragma unroll
    for (int r = 0; r < 8; r++) {
        ulonglong2 h01 = *(const ulonglong2*)&H0g[(size_t)(grow + r) * NN + c0];
        ulonglong2 h23 = *(const ulonglong2*)&H0g[(size_t)(grow + r) * NN + c0 + 4];
        acc[r][0] = h01.x; acc[r][1] = h01.y; acc[r][2] = h23.x; acc[r][3] = h23.y;
    }
    #pragma unroll
    for (int k = 0; k < TT; k++) {
        ulonglong2 a01 = *(ulonglong2*)&sA[k][c0];
        ulonglong2 a23 = *(ulonglong2*)&sA[k][c0 + 4];
        ulonglong2 s01 = *(ulonglong2*)&sS[k][c0];
        ulonglong2 s23 = *(ulonglong2*)&sS[k][c0 + 4];
        u64 av[4] = {a01.x, a01.y, a23.x, a23.y};
        u64 sv[4] = {s01.x, s01.y, s23.x, s23.y};
        float4 sr0 = *(float4*)&sS[k][grow];
        float4 sr1 = *(float4*)&sS[k][grow + 4];
        float4 ur0 = *(float4*)&sUn[k][lr0];
        float4 ur1 = *(float4*)&sUn[k][lr0 + 4];
        float srow[8] = {sr0.x, sr0.y, sr0.z, sr0.w, sr1.x, sr1.y, sr1.z, sr1.w};
        float urow[8] = {ur0.x, ur0.y, ur0.z, ur0.w, ur1.x, ur1.y, ur1.z, ur1.w};
        #pragma unroll
        for (int r = 0; r < 8; r++) {
            u64 s2 = pack2(srow[r], srow[r]);
            u64 u2 = pack2(urow[r], urow[r]);
            #pragma unroll
            for (int c = 0; c < 4; c++) {
                acc[r][c] = fma2(s2, av[c], acc[r][c]);
                acc[r][c] = fma2(u2, sv[c], acc[r][c]);
            }
        }
    }
    #pragma unroll
    for (int r = 0; r < 8; r++) {
        *(ulonglong2*)&ob[(size_t)(grow + r) * NN + c0] =
            make_ulonglong2(acc[r][0], acc[r][1]);
        *(ulonglong2*)&ob[(size_t)(grow + r) * NN + c0 + 4] =
            make_ulonglong2(acc[r][2], acc[r][3]);
    }
}

extern "C" void kernel_launch(void* const* d_in, const int* in_sizes, int n_in,
                              void* d_out, int out_size) {
    const float* H0    = (const float*)d_in[0];   // inv_hessian [192,192]
    const float* steps = (const float*)d_in[1];   // [12,8,32,192]
    const float* dgs   = (const float*)d_in[2];   // [12,8,32,192]
    float* out = (float*)d_out;                   // [8,32,192,192]

    kz_kernel<<<288, 256>>>(H0, dgs);
    ks_kernel<<<BE, 192>>>(steps, dgs);
    ke_kernel<<<BE * 3, 192>>>(H0, steps, out);
}

// round 15
// speedup vs baseline: 1.4858x; 1.1007x over previous
#include <cuda_runtime.h>

// LearnedBFGSSolver — 3 kernels:
//  kz: [U0|V0] = Y @ [H0^T | H0], 64x64 tiles (best measured FMA:LDS ratio),
//      K split in halves -> grid 288 (2 CTAs/SM). Partial buffers.
//  ks: per-pair Grams (padded rows) -> 12x12 scalar recursion -> A, Un.
//      Merges kz partial halves during load.
//  ke: H = H0 + S^T A + Un^T S rank-24 GEMM, conflict-free, grid 768.

#define NN 192
#define NP 196
#define TT 12
#define BE 256

typedef unsigned long long u64;

__device__ float g_U0a[TT * BE * NN];  // K-half 0 partial
__device__ float g_U0b[TT * BE * NN];  // K-half 1 partial
__device__ float g_V0a[TT * BE * NN];
__device__ float g_V0b[TT * BE * NN];
__device__ float g_A  [BE * TT * NN];
__device__ float g_Un [BE * TT * NN];

__device__ __forceinline__ u64 fma2(u64 a, u64 b, u64 c) {
    u64 d; asm("fma.rn.f32x2 %0, %1, %2, %3;" : "=l"(d) : "l"(a), "l"(b), "l"(c));
    return d;
}
__device__ __forceinline__ u64 pack2(float lo, float hi) {
    u64 d; asm("mov.b64 %0, {%1, %2};" : "=l"(d) : "f"(lo), "f"(hi));
    return d;
}
__device__ __forceinline__ void unpack2(u64 v, float& lo, float& hi) {
    asm("mov.b64 {%0, %1}, %2;" : "=f"(lo), "=f"(hi) : "l"(v));
}

// ---------------- K1: kz — 64x64 tiles, K-split, grid 288 ----------------
// U0[r][i] = sum_j Y[r][j] H0[i][j],  V0[r][i] = sum_j Y[r][j] H0[j][i].
__global__ void __launch_bounds__(256, 2)
kz_kernel(const float* __restrict__ H0g, const float* __restrict__ dgs)
{
    __shared__ float sYt[32][68];   // sYt[jj][rr] = Y[r0+rr][j0+jj]
    __shared__ float sBu[32][68];   // sBu[jj][ii] = H0[i0+ii][j0+jj]
    __shared__ float sBv[32][68];   // sBv[jj][ii] = H0[j0+jj][i0+ii]
    const int tid = threadIdx.x;
    const int kh  = blockIdx.x / 144;          // K half: 0 or 1
    const int rem = blockIdx.x % 144;
    const int rb  = rem % 48, cb = rem / 48;
    const int r0  = rb * 64, i0 = cb * 64;
    const int cgi = tid & 15;       // cols i0 + cgi*4 .. +3
    const int rgi = tid >> 4;       // rows r0 + rgi*4 .. +3

    u64 aU[4][2], aV[4][2];
    #pragma unroll
    for (int r = 0; r < 4; r++) {
        aU[r][0] = 0ull; aU[r][1] = 0ull;
        aV[r][0] = 0ull; aV[r][1] = 0ull;
    }

    for (int jt = kh * 3; jt < kh * 3 + 3; jt++) {
        const int j0 = jt * 32;
        __syncthreads();
        // sYt: 64 rows x 8 float4, transposed scatter
        #pragma unroll
        for (int n = 0; n < 2; n++) {
            int idx = n * 256 + tid;
            int rr = idx >> 3, q = idx & 7;
            float4 y4 = *(const float4*)&dgs[(size_t)(r0 + rr) * NN + j0 + 4 * q];
            sYt[4 * q + 0][rr] = y4.x;
            sYt[4 * q + 1][rr] = y4.y;
            sYt[4 * q + 2][rr] = y4.z;
            sYt[4 * q + 3][rr] = y4.w;
        }
        // sBu: H0[i0:i0+64][j0:j0+32], transposed scatter
        #pragma unroll
        for (int n = 0; n < 2; n++) {
            int idx = n * 256 + tid;
            int ii = idx >> 3, q = idx & 7;
            float4 h4 = *(const float4*)&H0g[(size_t)(i0 + ii) * NN + j0 + 4 * q];
            sBu[4 * q + 0][ii] = h4.x;
            sBu[4 * q + 1][ii] = h4.y;
            sBu[4 * q + 2][ii] = h4.z;
            sBu[4 * q + 3][ii] = h4.w;
        }
        // sBv: H0[j0:j0+32][i0:i0+64], direct float4
        #pragma unroll
        for (int n = 0; n < 2; n++) {
            int idx = n * 256 + tid;
            int jj = idx >> 4, q = idx & 15;
            float4 h4 = *(const float4*)&H0g[(size_t)(j0 + jj) * NN + i0 + 4 * q];
            *(float4*)&sBv[jj][4 * q] = h4;
        }
        __syncthreads();

        #pragma unroll 4
        for (int jj = 0; jj < 32; jj++) {
            float4 y4 = *(const float4*)&sYt[jj][rgi * 4];
            ulonglong2 bu = *(const ulonglong2*)&sBu[jj][cgi * 4];
            ulonglong2 bv = *(const ulonglong2*)&sBv[jj][cgi * 4];
            u64 y2[4] = {pack2(y4.x, y4.x), pack2(y4.y, y4.y),
                         pack2(y4.z, y4.z), pack2(y4.w, y4.w)};
            #pragma unroll
            for (int r = 0; r < 4; r++) {
                aU[r][0] = fma2(y2[r], bu.x, aU[r][0]);
                aU[r][1] = fma2(y2[r], bu.y, aU[r][1]);
                aV[r][0] = fma2(y2[r], bv.x, aV[r][0]);
                aV[r][1] = fma2(y2[r], bv.y, aV[r][1]);
            }
        }
    }

    float* dU = kh ? g_U0b : g_U0a;
    float* dV = kh ? g_V0b : g_V0a;
    #pragma unroll
    for (int rr = 0; rr < 4; rr++) {
        size_t off = (size_t)(r0 + rgi * 4 + rr) * NN + i0 + cgi * 4;
        float4 uo, vo;
        unpack2(aU[rr][0], uo.x, uo.y);
        unpack2(aU[rr][1], uo.z, uo.w);
        unpack2(aV[rr][0], vo.x, vo.y);
        unpack2(aV[rr][1], vo.z, vo.w);
        *(float4*)&dU[off] = uo;
        *(float4*)&dV[off] = vo;
    }
}

// ---------------- K2: ks — per-pair recursion, padded rows, merges halves ----------------
__global__ void __launch_bounds__(192)
ks_kernel(const float* __restrict__ steps, const float* __restrict__ dgs)
{
    __shared__ float sS[TT][NP], sY[TT][NP], sU0[TT][NP], sV0[TT][NP];
    __shared__ float sG1[TT][TT], sW[TT][TT];
    __shared__ float sCU[TT][TT], sCV[TT][TT], sB[TT][TT];
    __shared__ float sC1[TT], sC2[TT];

    const int tid = threadIdx.x;
    const int be  = blockIdx.x;

    for (int idx = tid; idx < TT * NN / 4; idx += 192) {
        int e = idx * 4;
        int k = e / NN, j = e % NN;
        size_t roff = (size_t)(k * BE + be) * NN + j;
        *(float4*)&sS[k][j] = *(const float4*)&steps[roff];
        *(float4*)&sY[k][j] = *(const float4*)&dgs[roff];
        float4 ua = *(const float4*)&g_U0a[roff];
        float4 ub = *(const float4*)&g_U0b[roff];
        float4 va = *(const float4*)&g_V0a[roff];
        float4 vb = *(const float4*)&g_V0b[roff];
        *(float4*)&sU0[k][j] = make_float4(ua.x + ub.x, ua.y + ub.y,
                                           ua.z + ub.z, ua.w + ub.w);
        *(float4*)&sV0[k][j] = make_float4(va.x + vb.x, va.y + vb.y,
                                           va.z + vb.z, va.w + vb.w);
    }
    __syncthreads();

    // Grams: G1 = S Y^T, W = V0 Y^T (2x2 cells/thread, 72 threads, padded rows)
    if (tid < 72) {
        int which = tid / 36;
        int cell  = tid % 36;
        int k0 = (cell / 6) * 2, t0 = (cell % 6) * 2;
        const float (*P)[NP] = which ? sV0 : sS;
        float a00 = 0.f, a01 = 0.f, a10 = 0.f, a11 = 0.f;
        for (int j = 0; j < NN; j += 4) {
            float4 p0 = *(const float4*)&P[k0][j];
            float4 p1 = *(const float4*)&P[k0 + 1][j];
            float4 q0 = *(const float4*)&sY[t0][j];
            float4 q1 = *(const float4*)&sY[t0 + 1][j];
            a00 += p0.x * q0.x + p0.y * q0.y + p0.z * q0.z + p0.w * q0.w;
            a01 += p0.x * q1.x + p0.y * q1.y + p0.z * q1.z + p0.w * q1.w;
            a10 += p1.x * q0.x + p1.y * q0.y + p1.z * q0.z + p1.w * q0.w;
            a11 += p1.x * q1.x + p1.y * q1.y + p1.z * q1.z + p1.w * q1.w;
        }
        float (*G)[TT] = which ? sW : sG1;
        G[k0][t0] = a00;     G[k0][t0 + 1] = a01;
        G[k0 + 1][t0] = a10; G[k0 + 1][t0 + 1] = a11;
    }
    __syncthreads();

    // Warp-0 scalar recursion, lane = column t
    if (tid < 32) {
        const int t = (tid < TT) ? tid : (TT - 1);
        float G1c[TT], Wc[TT], Wr[TT];
        float d2c[TT], d3c[TT];
        float c1v[TT], c2v[TT];
        float cuL[TT], cvL[TT], bL[TT];
        #pragma unroll
        for (int m = 0; m < TT; m++) {
            G1c[m] = sG1[m][t];
            Wc[m]  = sW[m][t];
            Wr[m]  = sW[t][m];
            cuL[m] = 0.f; cvL[m] = 0.f; bL[m] = 0.f;
        }
        #pragma unroll
        for (int k = 0; k < TT; k++) {
            if (k > 0) {
                const int m = k - 1;
                cuL[m] = c1v[m] * G1c[m] - c2v[m] * d2c[m];
                cvL[m] = c1v[m] * G1c[m] - c2v[m] * d3c[m];
                bL[m]  = -c2v[m] * G1c[m];
            }
            float x2 = Wc[k], x3 = Wr[k];
            #pragma unroll
            for (int m = 0; m < TT - 1; m++) {
                if (m < k) {
                    float cvk = __shfl_sync(0xFFFFFFFFu, cvL[m], k);
                    float cuk = __shfl_sync(0xFFFFFFFFu, cuL[m], k);
                    float bk  = __shfl_sync(0xFFFFFFFFu, bL[m],  k);
                    x2 += cvk * G1c[m] + bk * d2c[m];
                    x3 += cuk * G1c[m] + bk * d3c[m];
                }
            }
            d2c[k] = x2;
            d3c[k] = x3;
            float yHy  = __shfl_sync(0xFFFFFFFFu, x3, k);
            float sdot = __shfl_sync(0xFFFFFFFFu, G1c[k], k);
            float ic = (sdot != 0.0f) ? (1.0f / sdot) : 0.0f;
            c2v[k] = ic;
            c1v[k] = (sdot + yHy) * ic * ic;
        }
        if (tid < TT) {
            #pragma unroll
            for (int m = 0; m < TT - 1; m++) {
                sCU[m][t] = cuL[m];
                sCV[m][t] = cvL[m];
                sB[m][t]  = bL[m];
            }
        }
        if (tid == 0) {
            #pragma unroll
            for (int m = 0; m < TT; m++) { sC1[m] = c1v[m]; sC2[m] = c2v[m]; }
        }
    }
    __syncthreads();

    // Barrier-free per-element rebuild; emit A, Un (be-major)
    {
        const int i = tid;
        float s[TT], u[TT], v[TT];
        #pragma unroll
        for (int k = 0; k < TT; k++) {
            s[k] = sS[k][i];
            u[k] = sU0[k][i];
            v[k] = sV0[k][i];
        }
        #pragma unroll
        for (int t = 0; t < TT; t++) {
            #pragma unroll
            for (int k = 0; k < TT - 1; k++) {
                if (k < t) {
                    float bb = sB[k][t];
                    u[t] += sCU[k][t] * s[k] + bb * u[k];
                    v[t] += sCV[k][t] * s[k] + bb * v[k];
                }
            }
            float c1 = sC1[t], c2 = sC2[t];
            g_A [(size_t)(be * TT + t) * NN + i] = c1 * s[t] - c2 * v[t];
            g_Un[(size_t)(be * TT + t) * NN + i] = -c2 * u[t];
        }
    }
}

// ---------------- K3: ke — rank-24 epilogue GEMM ----------------
__global__ void __launch_bounds__(192)
ke_kernel(const float* __restrict__ H0g,
          const float* __restrict__ steps,
          float* __restrict__ out)
{
    __shared__ float sA[TT][NN];
    __shared__ float sS[TT][NN];
    __shared__ float sUn[TT][64];
    const int tid  = threadIdx.x;
    const int be   = blockIdx.x / 3;
    const int rblk = (blockIdx.x % 3) * 64;

    for (int idx = tid; idx < TT * NN / 4; idx += 192) {
        int e = idx * 4;
        int k = e / NN, j = e % NN;
        *(float4*)&sA[k][j] = *(const float4*)&g_A[(size_t)(be * TT + k) * NN + j];
        *(float4*)&sS[k][j] = *(const float4*)&steps[(size_t)(k * BE + be) * NN + j];
    }
    {
        int e = tid * 4;
        int k = e / 64, r = e % 64;
        *(float4*)&sUn[k][r] = *(const float4*)&g_Un[(size_t)(be * TT + k) * NN + rblk + r];
    }
    __syncthreads();

    const int cg = tid >> 3, rg = tid & 7;
    const int c0   = cg * 8;
    const int lr0  = rg * 8;
    const int grow = rblk + lr0;
    float* ob = out + (size_t)be * NN * NN;

    u64 acc[8][4];
    #pragma unroll
    for (int r = 0; r < 8; r++) {
        ulonglong2 h01 = *(const ulonglong2*)&H0g[(size_t)(grow + r) * NN + c0];
        ulonglong2 h23 = *(const ulonglong2*)&H0g[(size_t)(grow + r) * NN + c0 + 4];
        acc[r][0] = h01.x; acc[r][1] = h01.y; acc[r][2] = h23.x; acc[r][3] = h23.y;
    }
    #pragma unroll
    for (int k = 0; k < TT; k++) {
        ulonglong2 a01 = *(ulonglong2*)&sA[k][c0];
        ulonglong2 a23 = *(ulonglong2*)&sA[k][c0 + 4];
        ulonglong2 s01 = *(ulonglong2*)&sS[k][c0];
        ulonglong2 s23 = *(ulonglong2*)&sS[k][c0 + 4];
        u64 av[4] = {a01.x, a01.y, a23.x, a23.y};
        u64 sv[4] = {s01.x, s01.y, s23.x, s23.y};
        float4 sr0 = *(float4*)&sS[k][grow];
        float4 sr1 = *(float4*)&sS[k][grow + 4];
        float4 ur0 = *(float4*)&sUn[k][lr0];
        float4 ur1 = *(float4*)&sUn[k][lr0 + 4];
        float srow[8] = {sr0.x, sr0.y, sr0.z, sr0.w, sr1.x, sr1.y, sr1.z, sr1.w};
        float urow[8] = {ur0.x, ur0.y, ur0.z, ur0.w, ur1.x, ur1.y, ur1.z, ur1.w};
        #pragma unroll
        for (int r = 0; r < 8; r++) {
            u64 s2 = pack2(srow[r], srow[r]);
            u64 u2 = pack2(urow[r], urow[r]);
            #pragma unroll
            for (int c = 0; c < 4; c++) {
                acc[r][c] = fma2(s2, av[c], acc[r][c]);
                acc[r][c] = fma2(u2, sv[c], acc[r][c]);
            }
        }
    }
    #pragma unroll
    for (int r = 0; r < 8; r++) {
        *(ulonglong2*)&ob[(size_t)(grow + r) * NN + c0] =
            make_ulonglong2(acc[r][0], acc[r][1]);
        *(ulonglong2*)&ob[(size_t)(grow + r) * NN + c0 + 4] =
            make_ulonglong2(acc[r][2], acc[r][3]);
    }
}

extern "C" void kernel_launch(void* const* d_in, const int* in_sizes, int n_in,
                              void* d_out, int out_size) {
    const float* H0    = (const float*)d_in[0];   // inv_hessian [192,192]
    const float* steps = (const float*)d_in[1];   // [12,8,32,192]
    const float* dgs   = (const float*)d_in[2];   // [12,8,32,192]
    float* out = (float*)d_out;                   // [8,32,192,192]

    kz_kernel<<<288, 256>>>(H0, dgs);
    ks_kernel<<<BE, 192>>>(steps, dgs);
    ke_kernel<<<BE * 3, 192>>>(H0, steps, out);
}